// round 16
// baseline (speedup 1.0000x reference)
#include <cuda_runtime.h>
#include <cuda_fp16.h>
#include <math.h>

typedef unsigned int u32;

#define OPACITY_TH 0.01f
#define EARLY_TERM 1e-4f

// pack two floats to f16x2 in ONE instruction: low16 = f16(lo_f), high16 = f16(hi_f)
__device__ __forceinline__ u32 packh(float lo_f, float hi_f) {
    u32 r; asm("cvt.rn.f16x2.f32 %0, %1, %2;" : "=r"(r) : "f"(hi_f), "f"(lo_f)); return r;
}
__device__ __forceinline__ float2 unpackh(u32 v) {
    __half2 h = *reinterpret_cast<__half2*>(&v);
    return __half22float2(h);
}
// relu on a packed f16x2 (identical to relu-before-round for rn)
__device__ __forceinline__ u32 relu2(u32 x) {
    u32 r; asm("max.f16x2 %0, %1, %2;" : "=r"(r) : "r"(x), "r"(0u)); return r;
}

__device__ __forceinline__ void mma_f16(float& d0, float& d1, float& d2, float& d3,
                                        u32 a0, u32 a1, u32 a2, u32 a3,
                                        u32 b0, u32 b1) {
    asm volatile("mma.sync.aligned.m16n8k16.row.col.f32.f16.f16.f32 "
        "{%0,%1,%2,%3}, {%4,%5,%6,%7}, {%8,%9}, {%0,%1,%2,%3};"
        : "+f"(d0), "+f"(d1), "+f"(d2), "+f"(d3)
        : "r"(a0), "r"(a1), "r"(a2), "r"(a3), "r"(b0), "r"(b1));
}

// ---------------- precomputed globals (prep kernel output) ----------------
__device__ __align__(16) u32 g_Bq[4096];     // layer-2 B, nt-paired (R12 layout)
__device__ __align__(16) uint4 g_B1q[256];   // layer-1 B (R13 layout)
__device__ __align__(8)  uint2 g_WsF[256];   // sigma B frags: col0=ws, cols1-7=0
__device__ __align__(8)  uint2 g_B3q[128];   // layer-3 B frags: cols0-2 = rw2 r,g,b
__device__ float g_hconst[64];               // f_b2 @ r_w1[:64,:] + r_b1
__device__ float g_sconst[1];                // f_b2·s_w + s_b

__global__ void prep_kernel(const float* __restrict__ f_w1, const float* __restrict__ f_b1,
                            const float* __restrict__ f_w2, const float* __restrict__ f_b2,
                            const float* __restrict__ s_w,  const float* __restrict__ s_b,
                            const float* __restrict__ r_w1, const float* __restrict__ r_b1,
                            const float* __restrict__ r_w2)
{
    int i = blockIdx.x * blockDim.x + threadIdx.x;
    if (i < 2048) {
        int fid = i >> 5, lane = i & 31;
        int nt = fid >> 3, kt = fid & 7;
        int n = nt * 8 + (lane >> 2);
        int tq = lane & 3;
        int k0 = kt * 16 + 2 * tq;
        float v[4];
        #pragma unroll
        for (int e = 0; e < 4; e++) {
            int k = k0 + (e >> 1) * 8 + (e & 1);
            float s = 0.0f;
            #pragma unroll 8
            for (int t = 0; t < 64; t++) s += f_w2[k * 64 + t] * r_w1[t * 64 + n];
            v[e] = s;
        }
        int ntp = nt >> 1;
        int base = ((ntp * 8 + kt) * 32 + lane) * 4 + (nt & 1) * 2;
        g_Bq[base + 0] = packh(v[0], v[1]);
        g_Bq[base + 1] = packh(v[2], v[3]);
    } else if (i < 2304) {
        // layer-1 B fragments
        int ii = i - 2048;
        int j = ii >> 5, lane = ii & 31;
        int tq = lane & 3;
        u32 r[4];
        #pragma unroll
        for (int half = 0; half < 2; half++) {
            int nt = 2 * j + half;
            int n = nt * 8 + (lane >> 2);
            float wx = f_w1[0 * 128 + n], wy = f_w1[1 * 128 + n], wz = f_w1[2 * 128 + n];
            float bb = f_b1[n];
            float2 hxy = unpackh(packh(wx, wy));
            float2 hzb = unpackh(packh(wz, bb));
            float lwx = wx - hxy.x, lwy = wy - hxy.y;
            float lwz = wz - hzb.x, lbb = bb - hzb.y;
            u32 b0, b1;
            if (tq == 0)      { b0 = packh(wx, wy);  b1 = packh(lwx, lwy); }
            else if (tq == 1) { b0 = packh(wz, bb);  b1 = packh(lwz, 0.0f); }
            else if (tq == 2) { b0 = packh(wx, wy);  b1 = 0u; }
            else              { b0 = packh(wz, lbb); b1 = 0u; }
            r[2 * half] = b0; r[2 * half + 1] = b1;
        }
        g_B1q[j * 32 + lane] = make_uint4(r[0], r[1], r[2], r[3]);
    } else if (i < 2560) {
        // sigma B fragments (n8 tile, col 0 = ws)
        int ii = i - 2304;
        int kt = ii >> 5, lane = ii & 31;
        int n = lane >> 2, tq = lane & 3;
        uint2 o = make_uint2(0u, 0u);
        if (n == 0) {
            int k0 = kt * 16 + 2 * tq;
            float w[4];
            #pragma unroll
            for (int e = 0; e < 4; e++) {
                int k = k0 + (e >> 1) * 8 + (e & 1);
                float s = 0.0f;
                #pragma unroll 8
                for (int t = 0; t < 64; t++) s += f_w2[k * 64 + t] * s_w[t];
                w[e] = s;
            }
            o.x = packh(w[0], w[1]);
            o.y = packh(w[2], w[3]);
        }
        g_WsF[kt * 32 + lane] = o;
    } else if (i < 2688) {
        // layer-3 B fragments: cols 0..2 = r_w2 columns (r,g,b)
        int ii = i - 2560;
        int kt3 = ii >> 5, lane = ii & 31;
        int n = lane >> 2, tq = lane & 3;
        uint2 o = make_uint2(0u, 0u);
        if (n < 3) {
            int k0 = kt3 * 16 + 2 * tq;
            o.x = packh(r_w2[k0 * 3 + n],       r_w2[(k0 + 1) * 3 + n]);
            o.y = packh(r_w2[(k0 + 8) * 3 + n], r_w2[(k0 + 9) * 3 + n]);
        }
        g_B3q[kt3 * 32 + lane] = o;
    } else if (i < 2752) {
        int j = i - 2688;
        float s = r_b1[j];
        #pragma unroll 8
        for (int t = 0; t < 64; t++) s += f_b2[t] * r_w1[t * 64 + j];
        g_hconst[j] = s;
    } else if (i == 2752) {
        float s = s_b[0];
        for (int t = 0; t < 64; t++) s += f_b2[t] * s_w[t];
        g_sconst[0] = s;
    }
}

// ---------------- dynamic shared layout (bytes) ----------------
#define SM_BQ    0        // 16KB layer-2 B
#define SM_B1    16384    // 4KB layer-1 B
#define SM_WSF   20480    // 2KB sigma B frags
#define SM_B3    22528    // 1KB layer-3 B frags (uint2[128])
#define SM_HC    23552    // 256B hc[64] (per-ray)
#define SM_SIGB  23808    // sigma_pre[256] 1KB
#define SM_RGBB  24832    // rgbRaw[256] float4 4KB
#define SM_POS   28928    // positions[256] float4 4KB
#define SM_MISC  33024    // [0..2]=r_b2, [3]=sconst
#define SMEM_BYTES 33040

__device__ __forceinline__ float tmap(float u) {
    return (u < 0.5f) ? 2.0f * u : 1.0f / (2.0f - 2.0f * u);
}

#define USTEP ((257.0f / 258.0f) / 256.0f)

__device__ __forceinline__ void ray_pos(int s, float ox, float oy, float oz,
                                        float dx, float dy, float dz,
                                        float& px, float& py, float& pz) {
    float tv = tmap((float)s * USTEP);
    px = ox + dx * tv; py = oy + dy * tv; pz = oz + dz * tv;
    float nrm = sqrtf(px * px + py * py + pz * pz);
    float cs = (nrm <= 1.0f) ? 0.5f : (2.0f - 1.0f / nrm) / nrm * 0.5f;
    px *= cs; py *= cs; pz *= cs;
}

__device__ __forceinline__ float sample_grid(const float* __restrict__ grid,
                                             float px, float py, float pz) {
    float ixf = ((px + 1.0f) * 128.0f - 1.0f) * 0.5f;
    float iyf = ((py + 1.0f) * 128.0f - 1.0f) * 0.5f;
    float izf = ((pz + 1.0f) * 128.0f - 1.0f) * 0.5f;
    float fx0 = floorf(ixf), fy0 = floorf(iyf), fz0 = floorf(izf);
    int ix0 = (int)fx0, iy0 = (int)fy0, iz0 = (int)fz0;
    float fx = ixf - fx0, fy = iyf - fy0, fz = izf - fz0;
    float occ = 0.0f;
    #pragma unroll
    for (int dzc = 0; dzc < 2; dzc++) {
        int cz = iz0 + dzc;
        if (cz < 0 || cz >= 128) continue;
        float wz = dzc ? fz : 1.0f - fz;
        #pragma unroll
        for (int dyc = 0; dyc < 2; dyc++) {
            int cy = iy0 + dyc;
            if (cy < 0 || cy >= 128) continue;
            float wy = dyc ? fy : 1.0f - fy;
            #pragma unroll
            for (int dxc = 0; dxc < 2; dxc++) {
                int cx = ix0 + dxc;
                if (cx < 0 || cx >= 128) continue;
                float wx = dxc ? fx : 1.0f - fx;
                occ += wz * wy * wx * __ldg(&grid[(cz << 14) + (cy << 7) + cx]);
            }
        }
    }
    return occ;
}

// Layer-1 A fragments for one row (contracted position P).
__device__ __forceinline__ void build_a1(float4 P, int tq, u32& aL, u32& aH) {
    u32 c0 = packh(P.x, P.y);
    u32 c1 = packh(P.z, 1.0f);
    float2 fxy = unpackh(c0);
    float2 fz1 = unpackh(c1);
    u32 c2 = packh(P.x - fxy.x, P.y - fxy.y);
    u32 c3 = packh(P.z - fz1.x, 1.0f);
    aL = (tq < 2) ? ((tq == 1) ? c1 : c0) : ((tq == 3) ? c3 : c2);
    aH = (tq == 0) ? c0 : ((tq == 1) ? (c1 & 0xFFFFu) : 0u);
}

__global__ void __launch_bounds__(128, 5) nerf_render_kernel(
    const float* __restrict__ rays_o, const float* __restrict__ rays_d,
    const float* __restrict__ grid,
    const float* __restrict__ r_w1,
    const float* __restrict__ r_b2,
    float* __restrict__ out)
{
    extern __shared__ __align__(16) char smdyn[];
    __shared__ float wsumA[4], wsumB[4];
    __shared__ float wred[4][3];

    const int tid = threadIdx.x;
    const int wid = tid >> 5;
    const int lid = tid & 31;
    const int g   = lid >> 2;
    const int tq  = lid & 3;
    const int ray = blockIdx.x;

    const float ox = __ldg(&rays_o[ray * 3 + 0]);
    const float oy = __ldg(&rays_o[ray * 3 + 1]);
    const float oz = __ldg(&rays_o[ray * 3 + 2]);
    const float dx = __ldg(&rays_d[ray * 3 + 0]);
    const float dy = __ldg(&rays_d[ray * 3 + 1]);
    const float dz = __ldg(&rays_d[ray * 3 + 2]);

    float4* posb = (float4*)(smdyn + SM_POS);

    // ---- EARLY: positions + occupancy masks ----
    bool mA, mB;
    {
        float pxA, pyA, pzA, pxB, pyB, pzB;
        ray_pos(tid, ox, oy, oz, dx, dy, dz, pxA, pyA, pzA);
        ray_pos(tid + 128, ox, oy, oz, dx, dy, dz, pxB, pyB, pzB);
        posb[tid]       = make_float4(pxA, pyA, pzA, 0.0f);
        posb[tid + 128] = make_float4(pxB, pyB, pzB, 0.0f);
        mA = sample_grid(grid, pxA, pyA, pzA) > OPACITY_TH;
        mB = sample_grid(grid, pxB, pyB, pzB) > OPACITY_TH;
    }

    // ---- staging ----
    {
        uint4* dstB = (uint4*)(smdyn + SM_BQ);
        const uint4* srcB = (const uint4*)g_Bq;
        #pragma unroll
        for (int i = 0; i < 8; i++) dstB[tid + 128 * i] = srcB[tid + 128 * i];
        uint4* dstB1 = (uint4*)(smdyn + SM_B1);
        #pragma unroll
        for (int i = 0; i < 2; i++) dstB1[tid + 128 * i] = g_B1q[tid + 128 * i];
        uint2* dstWs = (uint2*)(smdyn + SM_WSF);
        #pragma unroll
        for (int i = 0; i < 2; i++) dstWs[tid + 128 * i] = g_WsF[tid + 128 * i];
        ((uint2*)(smdyn + SM_B3))[tid] = g_B3q[tid];
        if (tid < 64) {
            ((float*)(smdyn + SM_HC))[tid] = g_hconst[tid]
                      + dx * r_w1[64 * 64 + tid]
                      + dy * r_w1[65 * 64 + tid]
                      + dz * r_w1[66 * 64 + tid];
        }
        if (tid < 3)  ((float*)(smdyn + SM_MISC))[tid] = r_b2[tid];
        if (tid == 3) ((float*)(smdyn + SM_MISC))[3] = g_sconst[0];
    }
    __syncthreads();

    const uint4*  bp   = (const uint4*)(smdyn + SM_BQ);
    const uint4*  b1p  = (const uint4*)(smdyn + SM_B1);
    const uint2*  wsp  = (const uint2*)(smdyn + SM_WSF);
    const uint2*  b3p  = (const uint2*)(smdyn + SM_B3);
    const float*  hcp  = (const float*)(smdyn + SM_HC);
    float*        sigb = (float*)(smdyn + SM_SIGB);
    float*        rgbf = (float*)(smdyn + SM_RGBB);
    float4*       rgbb = (float4*)(smdyn + SM_RGBB);
    const float4* posv = (const float4*)(smdyn + SM_POS);
    const float rb0  = ((const float*)(smdyn + SM_MISC))[0];
    const float rb1  = ((const float*)(smdyn + SM_MISC))[1];
    const float rb2v = ((const float*)(smdyn + SM_MISC))[2];
    const float sconst = ((const float*)(smdyn + SM_MISC))[3];

    // ========== PHASE A: layer-1 MMA -> sigma MMA + layer-2 MMA -> layer-3 MMA
    #pragma unroll
    for (int mtp = 0; mtp < 2; mtp++) {
        const int tt0 = wid * 4 + 2 * mtp;
        const int r0 = 16 * tt0 + g;
        const int r1 = r0 + 8;
        const int r2 = r0 + 16;
        const int r3 = r0 + 24;

        u32 aL0, aH0, aL1, aH1, aL2, aH2, aL3, aH3;
        build_a1(posv[r0], tq, aL0, aH0);
        build_a1(posv[r1], tq, aL1, aH1);
        build_a1(posv[r2], tq, aL2, aH2);
        build_a1(posv[r3], tq, aL3, aH3);

        // layer-1 MMAs -> pack -> f16x2 relu -> layer-2 A frags
        u32 af0[8][4], af1[8][4];
        #pragma unroll
        for (int j = 0; j < 8; j++) {
            uint4 b = b1p[j * 32 + lid];
            float e0 = 0.0f, e1 = 0.0f, e2 = 0.0f, e3 = 0.0f;
            float f0 = 0.0f, f1 = 0.0f, f2 = 0.0f, f3 = 0.0f;
            float q0 = 0.0f, q1 = 0.0f, q2 = 0.0f, q3 = 0.0f;
            float s0 = 0.0f, s1 = 0.0f, s2 = 0.0f, s3 = 0.0f;
            mma_f16(e0, e1, e2, e3, aL0, aL1, aH0, aH1, b.x, b.y);
            mma_f16(f0, f1, f2, f3, aL0, aL1, aH0, aH1, b.z, b.w);
            mma_f16(q0, q1, q2, q3, aL2, aL3, aH2, aH3, b.x, b.y);
            mma_f16(s0, s1, s2, s3, aL2, aL3, aH2, aH3, b.z, b.w);
            af0[j][0] = relu2(packh(e0, e1));
            af0[j][1] = relu2(packh(e2, e3));
            af0[j][2] = relu2(packh(f0, f1));
            af0[j][3] = relu2(packh(f2, f3));
            af1[j][0] = relu2(packh(q0, q1));
            af1[j][1] = relu2(packh(q2, q3));
            af1[j][2] = relu2(packh(s0, s1));
            af1[j][3] = relu2(packh(s2, s3));
        }

        // sigma via n8 MMA (col 0 = ws)
        {
            float s00 = 0.0f, s01 = 0.0f, s02 = 0.0f, s03 = 0.0f;
            float s10 = 0.0f, s11 = 0.0f, s12 = 0.0f, s13 = 0.0f;
            #pragma unroll
            for (int kt = 0; kt < 8; kt++) {
                uint2 bs = wsp[kt * 32 + lid];
                mma_f16(s00, s01, s02, s03, af0[kt][0], af0[kt][1], af0[kt][2], af0[kt][3], bs.x, bs.y);
                mma_f16(s10, s11, s12, s13, af1[kt][0], af1[kt][1], af1[kt][2], af1[kt][3], bs.x, bs.y);
            }
            if (tq == 0) { sigb[r0] = s00; sigb[r1] = s02; sigb[r2] = s10; sigb[r3] = s12; }
        }

        // layer-2 MMAs -> +hc, pack, f16x2 relu -> layer-3 MMA
        float c00 = 0.0f, c01 = 0.0f, c02 = 0.0f, c03 = 0.0f;
        float c10 = 0.0f, c11 = 0.0f, c12 = 0.0f, c13 = 0.0f;
        #pragma unroll
        for (int ntp = 0; ntp < 4; ntp++) {
            float e00 = 0.0f, e01 = 0.0f, e02 = 0.0f, e03 = 0.0f;
            float e10 = 0.0f, e11 = 0.0f, e12 = 0.0f, e13 = 0.0f;
            float e20 = 0.0f, e21 = 0.0f, e22 = 0.0f, e23 = 0.0f;
            float e30 = 0.0f, e31 = 0.0f, e32 = 0.0f, e33 = 0.0f;
            const uint4* bnt = bp + ntp * 256 + lid;
            #pragma unroll
            for (int kt = 0; kt < 8; kt++) {
                uint4 b = bnt[kt * 32];
                mma_f16(e00, e01, e02, e03, af0[kt][0], af0[kt][1], af0[kt][2], af0[kt][3], b.x, b.y);
                mma_f16(e10, e11, e12, e13, af0[kt][0], af0[kt][1], af0[kt][2], af0[kt][3], b.z, b.w);
                mma_f16(e20, e21, e22, e23, af1[kt][0], af1[kt][1], af1[kt][2], af1[kt][3], b.x, b.y);
                mma_f16(e30, e31, e32, e33, af1[kt][0], af1[kt][1], af1[kt][2], af1[kt][3], b.z, b.w);
            }
            const int cE = ntp * 16 + 2 * tq;
            float2 hcE = *(const float2*)&hcp[cE];
            float2 hcO = *(const float2*)&hcp[cE + 8];
            uint2 b3 = b3p[ntp * 32 + lid];
            u32 x0 = relu2(packh(e00 + hcE.x, e01 + hcE.y));
            u32 x1 = relu2(packh(e02 + hcE.x, e03 + hcE.y));
            u32 x2 = relu2(packh(e10 + hcO.x, e11 + hcO.y));
            u32 x3 = relu2(packh(e12 + hcO.x, e13 + hcO.y));
            mma_f16(c00, c01, c02, c03, x0, x1, x2, x3, b3.x, b3.y);
            u32 y0 = relu2(packh(e20 + hcE.x, e21 + hcE.y));
            u32 y1 = relu2(packh(e22 + hcE.x, e23 + hcE.y));
            u32 y2 = relu2(packh(e30 + hcO.x, e31 + hcO.y));
            u32 y3 = relu2(packh(e32 + hcO.x, e33 + hcO.y));
            mma_f16(c10, c11, c12, c13, y0, y1, y2, y3, b3.x, b3.y);
        }
        // write weight-independent colors: tq0 holds (r,g), tq1 holds b
        if (tq == 0) {
            *(float2*)&rgbf[r0 * 4] = make_float2(1.0f / (1.0f + expf(-(c00 + rb0))),
                                                  1.0f / (1.0f + expf(-(c01 + rb1))));
            *(float2*)&rgbf[r1 * 4] = make_float2(1.0f / (1.0f + expf(-(c02 + rb0))),
                                                  1.0f / (1.0f + expf(-(c03 + rb1))));
            *(float2*)&rgbf[r2 * 4] = make_float2(1.0f / (1.0f + expf(-(c10 + rb0))),
                                                  1.0f / (1.0f + expf(-(c11 + rb1))));
            *(float2*)&rgbf[r3 * 4] = make_float2(1.0f / (1.0f + expf(-(c12 + rb0))),
                                                  1.0f / (1.0f + expf(-(c13 + rb1))));
        } else if (tq == 1) {
            rgbf[r0 * 4 + 2] = 1.0f / (1.0f + expf(-(c00 + rb2v)));
            rgbf[r1 * 4 + 2] = 1.0f / (1.0f + expf(-(c02 + rb2v)));
            rgbf[r2 * 4 + 2] = 1.0f / (1.0f + expf(-(c10 + rb2v)));
            rgbf[r3 * 4 + 2] = 1.0f / (1.0f + expf(-(c12 + rb2v)));
        }
    }
    __syncthreads();

    // ========== PHASE B: scan + weighted accumulation ========================
    float rgb0, rgb1, rgb2;
    {
        float tA  = tmap((float)tid * USTEP);
        float tA1 = tmap((float)(tid + 1) * USTEP);
        float tB  = tmap((float)(tid + 128) * USTEP);
        float tB1 = tmap((float)(tid + 129) * USTEP);
        float distA = tA1 - tA, distB = tB1 - tB;

        float preA = sigb[tid] + sconst;
        float preB = sigb[tid + 128] + sconst;
        float sigmaA = mA ? ((preA > 20.0f) ? preA : log1pf(expf(preA))) : 0.0f;
        float sigmaB = mB ? ((preB > 20.0f) ? preB : log1pf(expf(preB))) : 0.0f;

        float aA = -sigmaA * distA;
        float aB = -sigmaB * distB;
        float incA = aA, incB = aB;
        #pragma unroll
        for (int off = 1; off < 32; off <<= 1) {
            float yA = __shfl_up_sync(0xffffffffu, incA, off);
            float yB = __shfl_up_sync(0xffffffffu, incB, off);
            if (lid >= off) { incA += yA; incB += yB; }
        }
        if (lid == 31) { wsumA[wid] = incA; wsumB[wid] = incB; }
        __syncthreads();
        float offA = 0.0f, offB = 0.0f, totalA = 0.0f;
        #pragma unroll
        for (int i = 0; i < 4; i++) {
            float vA = wsumA[i];
            totalA += vA;
            if (i < wid) { offA += vA; offB += wsumB[i]; }
        }
        float exclA = offA + incA - aA;
        float exclB = totalA + offB + incB - aB;
        float transA = expf(exclA), transB = expf(exclB);
        float weightA = transA * (1.0f - expf(aA));
        float weightB = transB * (1.0f - expf(aB));
        float wA = (mA && transA > EARLY_TERM) ? weightA : 0.0f;
        float wB = (mB && transB > EARLY_TERM) ? weightB : 0.0f;

        float4 cA = rgbb[tid];
        float4 cB = rgbb[tid + 128];
        rgb0 = wA * cA.x + wB * cB.x;
        rgb1 = wA * cA.y + wB * cB.y;
        rgb2 = wA * cA.z + wB * cB.z;
    }

    // ---- deterministic block reduction ----
    #pragma unroll
    for (int off = 16; off > 0; off >>= 1) {
        rgb0 += __shfl_down_sync(0xffffffffu, rgb0, off);
        rgb1 += __shfl_down_sync(0xffffffffu, rgb1, off);
        rgb2 += __shfl_down_sync(0xffffffffu, rgb2, off);
    }
    if (lid == 0) { wred[wid][0] = rgb0; wred[wid][1] = rgb1; wred[wid][2] = rgb2; }
    __syncthreads();
    if (tid < 3) {
        float s = 0.0f;
        #pragma unroll
        for (int w = 0; w < 4; w++) s += wred[w][tid];
        out[ray * 3 + tid] = s;
    }
}

extern "C" void kernel_launch(void* const* d_in, const int* in_sizes, int n_in,
                              void* d_out, int out_size) {
    const float* rays_o = (const float*)d_in[0];
    const float* rays_d = (const float*)d_in[1];
    const float* grid   = (const float*)d_in[2];
    const float* f_w1   = (const float*)d_in[3];
    const float* f_b1   = (const float*)d_in[4];
    const float* f_w2   = (const float*)d_in[5];
    const float* f_b2   = (const float*)d_in[6];
    const float* s_w    = (const float*)d_in[7];
    const float* s_b    = (const float*)d_in[8];
    const float* r_w1   = (const float*)d_in[9];
    const float* r_b1   = (const float*)d_in[10];
    const float* r_w2   = (const float*)d_in[11];
    const float* r_b2   = (const float*)d_in[12];
    float* out = (float*)d_out;

    const int n_rays = in_sizes[0] / 3;

    prep_kernel<<<(2753 + 255) / 256, 256>>>(f_w1, f_b1, f_w2, f_b2, s_w, s_b, r_w1, r_b1, r_w2);

    cudaFuncSetAttribute(nerf_render_kernel,
                         cudaFuncAttributeMaxDynamicSharedMemorySize, SMEM_BYTES);
    nerf_render_kernel<<<n_rays, 128, SMEM_BYTES>>>(
        rays_o, rays_d, grid, r_w1, r_b2, out);
}

// round 17
// speedup vs baseline: 1.1751x; 1.1751x over previous
#include <cuda_runtime.h>
#include <cuda_fp16.h>
#include <math.h>

typedef unsigned int u32;

#define OPACITY_TH 0.01f
#define EARLY_TERM 1e-4f

// pack two floats to f16x2 in ONE instruction: low16 = f16(lo_f), high16 = f16(hi_f)
__device__ __forceinline__ u32 packh(float lo_f, float hi_f) {
    u32 r; asm("cvt.rn.f16x2.f32 %0, %1, %2;" : "=r"(r) : "f"(hi_f), "f"(lo_f)); return r;
}
__device__ __forceinline__ float2 unpackh(u32 v) {
    __half2 h = *reinterpret_cast<__half2*>(&v);
    return __half22float2(h);
}
// relu on a packed f16x2 (identical to relu-before-round for rn)
__device__ __forceinline__ u32 relu2(u32 x) {
    u32 r; asm("max.f16x2 %0, %1, %2;" : "=r"(r) : "r"(x), "r"(0u)); return r;
}

__device__ __forceinline__ void mma_f16(float& d0, float& d1, float& d2, float& d3,
                                        u32 a0, u32 a1, u32 a2, u32 a3,
                                        u32 b0, u32 b1) {
    asm volatile("mma.sync.aligned.m16n8k16.row.col.f32.f16.f16.f32 "
        "{%0,%1,%2,%3}, {%4,%5,%6,%7}, {%8,%9}, {%0,%1,%2,%3};"
        : "+f"(d0), "+f"(d1), "+f"(d2), "+f"(d3)
        : "r"(a0), "r"(a1), "r"(a2), "r"(a3), "r"(b0), "r"(b1));
}

// ---------------- precomputed globals (prep kernel output) ----------------
__device__ __align__(16) u32 g_Bq[4096];     // layer-2 B, nt-paired (R12 layout)
__device__ __align__(16) uint4 g_B1q[256];   // layer-1 B (R13 layout)
__device__ __align__(8)  uint2 g_WsF[256];   // sigma B frags: col0=ws, cols1-7=0
__device__ __align__(8)  uint2 g_B3q[128];   // layer-3 B frags: cols0-2 = rw2 r,g,b
__device__ float g_hconst[64];               // f_b2 @ r_w1[:64,:] + r_b1
__device__ float g_sconst[1];                // f_b2·s_w + s_b

__global__ void prep_kernel(const float* __restrict__ f_w1, const float* __restrict__ f_b1,
                            const float* __restrict__ f_w2, const float* __restrict__ f_b2,
                            const float* __restrict__ s_w,  const float* __restrict__ s_b,
                            const float* __restrict__ r_w1, const float* __restrict__ r_b1,
                            const float* __restrict__ r_w2)
{
    int i = blockIdx.x * blockDim.x + threadIdx.x;
    if (i < 2048) {
        int fid = i >> 5, lane = i & 31;
        int nt = fid >> 3, kt = fid & 7;
        int n = nt * 8 + (lane >> 2);
        int tq = lane & 3;
        int k0 = kt * 16 + 2 * tq;
        float v[4];
        #pragma unroll
        for (int e = 0; e < 4; e++) {
            int k = k0 + (e >> 1) * 8 + (e & 1);
            float s = 0.0f;
            #pragma unroll 8
            for (int t = 0; t < 64; t++) s += f_w2[k * 64 + t] * r_w1[t * 64 + n];
            v[e] = s;
        }
        int ntp = nt >> 1;
        int base = ((ntp * 8 + kt) * 32 + lane) * 4 + (nt & 1) * 2;
        g_Bq[base + 0] = packh(v[0], v[1]);
        g_Bq[base + 1] = packh(v[2], v[3]);
    } else if (i < 2304) {
        // layer-1 B fragments
        int ii = i - 2048;
        int j = ii >> 5, lane = ii & 31;
        int tq = lane & 3;
        u32 r[4];
        #pragma unroll
        for (int half = 0; half < 2; half++) {
            int nt = 2 * j + half;
            int n = nt * 8 + (lane >> 2);
            float wx = f_w1[0 * 128 + n], wy = f_w1[1 * 128 + n], wz = f_w1[2 * 128 + n];
            float bb = f_b1[n];
            float2 hxy = unpackh(packh(wx, wy));
            float2 hzb = unpackh(packh(wz, bb));
            float lwx = wx - hxy.x, lwy = wy - hxy.y;
            float lwz = wz - hzb.x, lbb = bb - hzb.y;
            u32 b0, b1;
            if (tq == 0)      { b0 = packh(wx, wy);  b1 = packh(lwx, lwy); }
            else if (tq == 1) { b0 = packh(wz, bb);  b1 = packh(lwz, 0.0f); }
            else if (tq == 2) { b0 = packh(wx, wy);  b1 = 0u; }
            else              { b0 = packh(wz, lbb); b1 = 0u; }
            r[2 * half] = b0; r[2 * half + 1] = b1;
        }
        g_B1q[j * 32 + lane] = make_uint4(r[0], r[1], r[2], r[3]);
    } else if (i < 2560) {
        // sigma B fragments (n8 tile, col 0 = ws)
        int ii = i - 2304;
        int kt = ii >> 5, lane = ii & 31;
        int n = lane >> 2, tq = lane & 3;
        uint2 o = make_uint2(0u, 0u);
        if (n == 0) {
            int k0 = kt * 16 + 2 * tq;
            float w[4];
            #pragma unroll
            for (int e = 0; e < 4; e++) {
                int k = k0 + (e >> 1) * 8 + (e & 1);
                float s = 0.0f;
                #pragma unroll 8
                for (int t = 0; t < 64; t++) s += f_w2[k * 64 + t] * s_w[t];
                w[e] = s;
            }
            o.x = packh(w[0], w[1]);
            o.y = packh(w[2], w[3]);
        }
        g_WsF[kt * 32 + lane] = o;
    } else if (i < 2688) {
        // layer-3 B fragments: cols 0..2 = r_w2 columns (r,g,b)
        int ii = i - 2560;
        int kt3 = ii >> 5, lane = ii & 31;
        int n = lane >> 2, tq = lane & 3;
        uint2 o = make_uint2(0u, 0u);
        if (n < 3) {
            int k0 = kt3 * 16 + 2 * tq;
            o.x = packh(r_w2[k0 * 3 + n],       r_w2[(k0 + 1) * 3 + n]);
            o.y = packh(r_w2[(k0 + 8) * 3 + n], r_w2[(k0 + 9) * 3 + n]);
        }
        g_B3q[kt3 * 32 + lane] = o;
    } else if (i < 2752) {
        int j = i - 2688;
        float s = r_b1[j];
        #pragma unroll 8
        for (int t = 0; t < 64; t++) s += f_b2[t] * r_w1[t * 64 + j];
        g_hconst[j] = s;
    } else if (i == 2752) {
        float s = s_b[0];
        for (int t = 0; t < 64; t++) s += f_b2[t] * s_w[t];
        g_sconst[0] = s;
    }
}

// ---------------- dynamic shared layout (bytes) ----------------
#define SM_BQ    0        // 16KB layer-2 B
#define SM_B1    16384    // 4KB layer-1 B
#define SM_WSF   20480    // 2KB sigma B frags
#define SM_B3    22528    // 1KB layer-3 B frags (uint2[128])
#define SM_HC    23552    // 256B hc[64] (per-ray)
#define SM_SIGB  23808    // sigma_pre[256] 1KB
#define SM_RGBB  24832    // rgbRaw[256] float4 4KB
#define SM_POS   28928    // positions[256] float4 4KB
#define SM_MISC  33024    // [0..2]=r_b2, [3]=sconst
#define SMEM_BYTES 33040

__device__ __forceinline__ float tmap(float u) {
    return (u < 0.5f) ? 2.0f * u : 1.0f / (2.0f - 2.0f * u);
}

#define USTEP ((257.0f / 258.0f) / 256.0f)

__device__ __forceinline__ void ray_pos(int s, float ox, float oy, float oz,
                                        float dx, float dy, float dz,
                                        float& px, float& py, float& pz) {
    float tv = tmap((float)s * USTEP);
    px = ox + dx * tv; py = oy + dy * tv; pz = oz + dz * tv;
    float nrm = sqrtf(px * px + py * py + pz * pz);
    float cs = (nrm <= 1.0f) ? 0.5f : (2.0f - 1.0f / nrm) / nrm * 0.5f;
    px *= cs; py *= cs; pz *= cs;
}

__device__ __forceinline__ float sample_grid(const float* __restrict__ grid,
                                             float px, float py, float pz) {
    float ixf = ((px + 1.0f) * 128.0f - 1.0f) * 0.5f;
    float iyf = ((py + 1.0f) * 128.0f - 1.0f) * 0.5f;
    float izf = ((pz + 1.0f) * 128.0f - 1.0f) * 0.5f;
    float fx0 = floorf(ixf), fy0 = floorf(iyf), fz0 = floorf(izf);
    int ix0 = (int)fx0, iy0 = (int)fy0, iz0 = (int)fz0;
    float fx = ixf - fx0, fy = iyf - fy0, fz = izf - fz0;
    float occ = 0.0f;
    #pragma unroll
    for (int dzc = 0; dzc < 2; dzc++) {
        int cz = iz0 + dzc;
        if (cz < 0 || cz >= 128) continue;
        float wz = dzc ? fz : 1.0f - fz;
        #pragma unroll
        for (int dyc = 0; dyc < 2; dyc++) {
            int cy = iy0 + dyc;
            if (cy < 0 || cy >= 128) continue;
            float wy = dyc ? fy : 1.0f - fy;
            #pragma unroll
            for (int dxc = 0; dxc < 2; dxc++) {
                int cx = ix0 + dxc;
                if (cx < 0 || cx >= 128) continue;
                float wx = dxc ? fx : 1.0f - fx;
                occ += wz * wy * wx * __ldg(&grid[(cz << 14) + (cy << 7) + cx]);
            }
        }
    }
    return occ;
}

// Layer-1 A fragments for one row (contracted position P).
__device__ __forceinline__ void build_a1(float4 P, int tq, u32& aL, u32& aH) {
    u32 c0 = packh(P.x, P.y);
    u32 c1 = packh(P.z, 1.0f);
    float2 fxy = unpackh(c0);
    float2 fz1 = unpackh(c1);
    u32 c2 = packh(P.x - fxy.x, P.y - fxy.y);
    u32 c3 = packh(P.z - fz1.x, 1.0f);
    aL = (tq < 2) ? ((tq == 1) ? c1 : c0) : ((tq == 3) ? c3 : c2);
    aH = (tq == 0) ? c0 : ((tq == 1) ? (c1 & 0xFFFFu) : 0u);
}

__global__ void __launch_bounds__(128, 4) nerf_render_kernel(
    const float* __restrict__ rays_o, const float* __restrict__ rays_d,
    const float* __restrict__ grid,
    const float* __restrict__ r_w1,
    const float* __restrict__ r_b2,
    float* __restrict__ out)
{
    extern __shared__ __align__(16) char smdyn[];
    __shared__ float wsumA[4], wsumB[4];
    __shared__ float wred[4][3];

    const int tid = threadIdx.x;
    const int wid = tid >> 5;
    const int lid = tid & 31;
    const int g   = lid >> 2;
    const int tq  = lid & 3;
    const int ray = blockIdx.x;

    const float ox = __ldg(&rays_o[ray * 3 + 0]);
    const float oy = __ldg(&rays_o[ray * 3 + 1]);
    const float oz = __ldg(&rays_o[ray * 3 + 2]);
    const float dx = __ldg(&rays_d[ray * 3 + 0]);
    const float dy = __ldg(&rays_d[ray * 3 + 1]);
    const float dz = __ldg(&rays_d[ray * 3 + 2]);

    float4* posb = (float4*)(smdyn + SM_POS);

    // ---- EARLY: positions + occupancy masks ----
    bool mA, mB;
    {
        float pxA, pyA, pzA, pxB, pyB, pzB;
        ray_pos(tid, ox, oy, oz, dx, dy, dz, pxA, pyA, pzA);
        ray_pos(tid + 128, ox, oy, oz, dx, dy, dz, pxB, pyB, pzB);
        posb[tid]       = make_float4(pxA, pyA, pzA, 0.0f);
        posb[tid + 128] = make_float4(pxB, pyB, pzB, 0.0f);
        mA = sample_grid(grid, pxA, pyA, pzA) > OPACITY_TH;
        mB = sample_grid(grid, pxB, pyB, pzB) > OPACITY_TH;
    }

    // ---- staging ----
    {
        uint4* dstB = (uint4*)(smdyn + SM_BQ);
        const uint4* srcB = (const uint4*)g_Bq;
        #pragma unroll
        for (int i = 0; i < 8; i++) dstB[tid + 128 * i] = srcB[tid + 128 * i];
        uint4* dstB1 = (uint4*)(smdyn + SM_B1);
        #pragma unroll
        for (int i = 0; i < 2; i++) dstB1[tid + 128 * i] = g_B1q[tid + 128 * i];
        uint2* dstWs = (uint2*)(smdyn + SM_WSF);
        #pragma unroll
        for (int i = 0; i < 2; i++) dstWs[tid + 128 * i] = g_WsF[tid + 128 * i];
        ((uint2*)(smdyn + SM_B3))[tid] = g_B3q[tid];
        if (tid < 64) {
            ((float*)(smdyn + SM_HC))[tid] = g_hconst[tid]
                      + dx * r_w1[64 * 64 + tid]
                      + dy * r_w1[65 * 64 + tid]
                      + dz * r_w1[66 * 64 + tid];
        }
        if (tid < 3)  ((float*)(smdyn + SM_MISC))[tid] = r_b2[tid];
        if (tid == 3) ((float*)(smdyn + SM_MISC))[3] = g_sconst[0];
    }
    __syncthreads();

    const uint4*  bp   = (const uint4*)(smdyn + SM_BQ);
    const uint4*  b1p  = (const uint4*)(smdyn + SM_B1);
    const uint2*  wsp  = (const uint2*)(smdyn + SM_WSF);
    const uint2*  b3p  = (const uint2*)(smdyn + SM_B3);
    const float*  hcp  = (const float*)(smdyn + SM_HC);
    float*        sigb = (float*)(smdyn + SM_SIGB);
    float*        rgbf = (float*)(smdyn + SM_RGBB);
    float4*       rgbb = (float4*)(smdyn + SM_RGBB);
    const float4* posv = (const float4*)(smdyn + SM_POS);
    const float rb0  = ((const float*)(smdyn + SM_MISC))[0];
    const float rb1  = ((const float*)(smdyn + SM_MISC))[1];
    const float rb2v = ((const float*)(smdyn + SM_MISC))[2];
    const float sconst = ((const float*)(smdyn + SM_MISC))[3];

    // ========== PHASE A: layer-1 MMA -> sigma MMA + layer-2 MMA -> layer-3 MMA
    #pragma unroll
    for (int mtp = 0; mtp < 2; mtp++) {
        const int tt0 = wid * 4 + 2 * mtp;
        const int r0 = 16 * tt0 + g;
        const int r1 = r0 + 8;
        const int r2 = r0 + 16;
        const int r3 = r0 + 24;

        u32 aL0, aH0, aL1, aH1, aL2, aH2, aL3, aH3;
        build_a1(posv[r0], tq, aL0, aH0);
        build_a1(posv[r1], tq, aL1, aH1);
        build_a1(posv[r2], tq, aL2, aH2);
        build_a1(posv[r3], tq, aL3, aH3);

        // layer-1 MMAs -> pack -> f16x2 relu -> layer-2 A frags
        u32 af0[8][4], af1[8][4];
        #pragma unroll
        for (int j = 0; j < 8; j++) {
            uint4 b = b1p[j * 32 + lid];
            float e0 = 0.0f, e1 = 0.0f, e2 = 0.0f, e3 = 0.0f;
            float f0 = 0.0f, f1 = 0.0f, f2 = 0.0f, f3 = 0.0f;
            float q0 = 0.0f, q1 = 0.0f, q2 = 0.0f, q3 = 0.0f;
            float s0 = 0.0f, s1 = 0.0f, s2 = 0.0f, s3 = 0.0f;
            mma_f16(e0, e1, e2, e3, aL0, aL1, aH0, aH1, b.x, b.y);
            mma_f16(f0, f1, f2, f3, aL0, aL1, aH0, aH1, b.z, b.w);
            mma_f16(q0, q1, q2, q3, aL2, aL3, aH2, aH3, b.x, b.y);
            mma_f16(s0, s1, s2, s3, aL2, aL3, aH2, aH3, b.z, b.w);
            af0[j][0] = relu2(packh(e0, e1));
            af0[j][1] = relu2(packh(e2, e3));
            af0[j][2] = relu2(packh(f0, f1));
            af0[j][3] = relu2(packh(f2, f3));
            af1[j][0] = relu2(packh(q0, q1));
            af1[j][1] = relu2(packh(q2, q3));
            af1[j][2] = relu2(packh(s0, s1));
            af1[j][3] = relu2(packh(s2, s3));
        }

        // sigma via n8 MMA (col 0 = ws)
        {
            float s00 = 0.0f, s01 = 0.0f, s02 = 0.0f, s03 = 0.0f;
            float s10 = 0.0f, s11 = 0.0f, s12 = 0.0f, s13 = 0.0f;
            #pragma unroll
            for (int kt = 0; kt < 8; kt++) {
                uint2 bs = wsp[kt * 32 + lid];
                mma_f16(s00, s01, s02, s03, af0[kt][0], af0[kt][1], af0[kt][2], af0[kt][3], bs.x, bs.y);
                mma_f16(s10, s11, s12, s13, af1[kt][0], af1[kt][1], af1[kt][2], af1[kt][3], bs.x, bs.y);
            }
            if (tq == 0) { sigb[r0] = s00; sigb[r1] = s02; sigb[r2] = s10; sigb[r3] = s12; }
        }

        // layer-2 MMAs -> +hc, pack, f16x2 relu -> layer-3 MMA
        float c00 = 0.0f, c01 = 0.0f, c02 = 0.0f, c03 = 0.0f;
        float c10 = 0.0f, c11 = 0.0f, c12 = 0.0f, c13 = 0.0f;
        #pragma unroll
        for (int ntp = 0; ntp < 4; ntp++) {
            float e00 = 0.0f, e01 = 0.0f, e02 = 0.0f, e03 = 0.0f;
            float e10 = 0.0f, e11 = 0.0f, e12 = 0.0f, e13 = 0.0f;
            float e20 = 0.0f, e21 = 0.0f, e22 = 0.0f, e23 = 0.0f;
            float e30 = 0.0f, e31 = 0.0f, e32 = 0.0f, e33 = 0.0f;
            const uint4* bnt = bp + ntp * 256 + lid;
            #pragma unroll
            for (int kt = 0; kt < 8; kt++) {
                uint4 b = bnt[kt * 32];
                mma_f16(e00, e01, e02, e03, af0[kt][0], af0[kt][1], af0[kt][2], af0[kt][3], b.x, b.y);
                mma_f16(e10, e11, e12, e13, af0[kt][0], af0[kt][1], af0[kt][2], af0[kt][3], b.z, b.w);
                mma_f16(e20, e21, e22, e23, af1[kt][0], af1[kt][1], af1[kt][2], af1[kt][3], b.x, b.y);
                mma_f16(e30, e31, e32, e33, af1[kt][0], af1[kt][1], af1[kt][2], af1[kt][3], b.z, b.w);
            }
            const int cE = ntp * 16 + 2 * tq;
            float2 hcE = *(const float2*)&hcp[cE];
            float2 hcO = *(const float2*)&hcp[cE + 8];
            uint2 b3 = b3p[ntp * 32 + lid];
            u32 x0 = relu2(packh(e00 + hcE.x, e01 + hcE.y));
            u32 x1 = relu2(packh(e02 + hcE.x, e03 + hcE.y));
            u32 x2 = relu2(packh(e10 + hcO.x, e11 + hcO.y));
            u32 x3 = relu2(packh(e12 + hcO.x, e13 + hcO.y));
            mma_f16(c00, c01, c02, c03, x0, x1, x2, x3, b3.x, b3.y);
            u32 y0 = relu2(packh(e20 + hcE.x, e21 + hcE.y));
            u32 y1 = relu2(packh(e22 + hcE.x, e23 + hcE.y));
            u32 y2 = relu2(packh(e30 + hcO.x, e31 + hcO.y));
            u32 y3 = relu2(packh(e32 + hcO.x, e33 + hcO.y));
            mma_f16(c10, c11, c12, c13, y0, y1, y2, y3, b3.x, b3.y);
        }
        // write weight-independent colors: tq0 holds (r,g), tq1 holds b
        if (tq == 0) {
            *(float2*)&rgbf[r0 * 4] = make_float2(1.0f / (1.0f + expf(-(c00 + rb0))),
                                                  1.0f / (1.0f + expf(-(c01 + rb1))));
            *(float2*)&rgbf[r1 * 4] = make_float2(1.0f / (1.0f + expf(-(c02 + rb0))),
                                                  1.0f / (1.0f + expf(-(c03 + rb1))));
            *(float2*)&rgbf[r2 * 4] = make_float2(1.0f / (1.0f + expf(-(c10 + rb0))),
                                                  1.0f / (1.0f + expf(-(c11 + rb1))));
            *(float2*)&rgbf[r3 * 4] = make_float2(1.0f / (1.0f + expf(-(c12 + rb0))),
                                                  1.0f / (1.0f + expf(-(c13 + rb1))));
        } else if (tq == 1) {
            rgbf[r0 * 4 + 2] = 1.0f / (1.0f + expf(-(c00 + rb2v)));
            rgbf[r1 * 4 + 2] = 1.0f / (1.0f + expf(-(c02 + rb2v)));
            rgbf[r2 * 4 + 2] = 1.0f / (1.0f + expf(-(c10 + rb2v)));
            rgbf[r3 * 4 + 2] = 1.0f / (1.0f + expf(-(c12 + rb2v)));
        }
    }
    __syncthreads();

    // ========== PHASE B: scan + weighted accumulation ========================
    float rgb0, rgb1, rgb2;
    {
        float tA  = tmap((float)tid * USTEP);
        float tA1 = tmap((float)(tid + 1) * USTEP);
        float tB  = tmap((float)(tid + 128) * USTEP);
        float tB1 = tmap((float)(tid + 129) * USTEP);
        float distA = tA1 - tA, distB = tB1 - tB;

        float preA = sigb[tid] + sconst;
        float preB = sigb[tid + 128] + sconst;
        float sigmaA = mA ? ((preA > 20.0f) ? preA : log1pf(expf(preA))) : 0.0f;
        float sigmaB = mB ? ((preB > 20.0f) ? preB : log1pf(expf(preB))) : 0.0f;

        float aA = -sigmaA * distA;
        float aB = -sigmaB * distB;
        float incA = aA, incB = aB;
        #pragma unroll
        for (int off = 1; off < 32; off <<= 1) {
            float yA = __shfl_up_sync(0xffffffffu, incA, off);
            float yB = __shfl_up_sync(0xffffffffu, incB, off);
            if (lid >= off) { incA += yA; incB += yB; }
        }
        if (lid == 31) { wsumA[wid] = incA; wsumB[wid] = incB; }
        __syncthreads();
        float offA = 0.0f, offB = 0.0f, totalA = 0.0f;
        #pragma unroll
        for (int i = 0; i < 4; i++) {
            float vA = wsumA[i];
            totalA += vA;
            if (i < wid) { offA += vA; offB += wsumB[i]; }
        }
        float exclA = offA + incA - aA;
        float exclB = totalA + offB + incB - aB;
        float transA = expf(exclA), transB = expf(exclB);
        float weightA = transA * (1.0f - expf(aA));
        float weightB = transB * (1.0f - expf(aB));
        float wA = (mA && transA > EARLY_TERM) ? weightA : 0.0f;
        float wB = (mB && transB > EARLY_TERM) ? weightB : 0.0f;

        float4 cA = rgbb[tid];
        float4 cB = rgbb[tid + 128];
        rgb0 = wA * cA.x + wB * cB.x;
        rgb1 = wA * cA.y + wB * cB.y;
        rgb2 = wA * cA.z + wB * cB.z;
    }

    // ---- deterministic block reduction ----
    #pragma unroll
    for (int off = 16; off > 0; off >>= 1) {
        rgb0 += __shfl_down_sync(0xffffffffu, rgb0, off);
        rgb1 += __shfl_down_sync(0xffffffffu, rgb1, off);
        rgb2 += __shfl_down_sync(0xffffffffu, rgb2, off);
    }
    if (lid == 0) { wred[wid][0] = rgb0; wred[wid][1] = rgb1; wred[wid][2] = rgb2; }
    __syncthreads();
    if (tid < 3) {
        float s = 0.0f;
        #pragma unroll
        for (int w = 0; w < 4; w++) s += wred[w][tid];
        out[ray * 3 + tid] = s;
    }
}

extern "C" void kernel_launch(void* const* d_in, const int* in_sizes, int n_in,
                              void* d_out, int out_size) {
    const float* rays_o = (const float*)d_in[0];
    const float* rays_d = (const float*)d_in[1];
    const float* grid   = (const float*)d_in[2];
    const float* f_w1   = (const float*)d_in[3];
    const float* f_b1   = (const float*)d_in[4];
    const float* f_w2   = (const float*)d_in[5];
    const float* f_b2   = (const float*)d_in[6];
    const float* s_w    = (const float*)d_in[7];
    const float* s_b    = (const float*)d_in[8];
    const float* r_w1   = (const float*)d_in[9];
    const float* r_b1   = (const float*)d_in[10];
    const float* r_w2   = (const float*)d_in[11];
    const float* r_b2   = (const float*)d_in[12];
    float* out = (float*)d_out;

    const int n_rays = in_sizes[0] / 3;

    prep_kernel<<<(2753 + 255) / 256, 256>>>(f_w1, f_b1, f_w2, f_b2, s_w, s_b, r_w1, r_b1, r_w2);

    cudaFuncSetAttribute(nerf_render_kernel,
                         cudaFuncAttributeMaxDynamicSharedMemorySize, SMEM_BYTES);
    nerf_render_kernel<<<n_rays, 128, SMEM_BYTES>>>(
        rays_o, rays_d, grid, r_w1, r_b2, out);
}